// round 10
// baseline (speedup 1.0000x reference)
#include <cuda_runtime.h>
#include <cuda_fp16.h>
#include <cstdint>

// ---------------------------------------------------------------------------
// WindowAttention (reference semantics):
//   qkv = window_gather(x) @ w_qkv^T          [100352 x 768]
//   per token: A[h,e] = softmax_e(q_h . k_e / sqrt(32));  o_h = sum_e A[h,e] v_e
//   att layout per window: h*1568 + s*32 + d  (swapaxes(1,2) flatten)
//   out = att @ w_proj^T + b, window-scattered back to (32,56,56,256)
//
// GEMMs: fp16 m16n8k16. Staging LDG fp32 -> cvt once -> STS fp16 smem
// (pad-40-half rows: conflict-free for ldmatrix). Consumers: ldmatrix.x4.
// Register-prefetch double buffering, one barrier per K-chunk.
// ---------------------------------------------------------------------------

#define M_TOK 100352
#define KDIM  256
#define QKV_N 768

__device__ float g_qkv[(size_t)M_TOK * QKV_N];
__device__ float g_att[(size_t)M_TOK * KDIM];

__device__ __forceinline__ int row_offset(int n) {
    int w  = n / 49;
    int s  = n - w * 49;
    int b  = w >> 6;
    int wh = (w >> 3) & 7;
    int ww = w & 7;
    int r  = s / 7;
    int cc = s - r * 7;
    int hh = wh * 7 + r;
    int wc = ww * 7 + cc;
    return ((b * 56 + hh) * 56 + wc) * 256;
}

#define TBM 128
#define TBN 128
#define TBK 32
#define PADH 40                       // halves per row (80B) -> conflict-free
#define BUFB (128 * PADH * 2)         // bytes per smem buffer per matrix

__device__ __forceinline__ uint32_t pkh2(float x, float y) {
    __half2 h = __floats2half2_rn(x, y);   // .x = low
    return *reinterpret_cast<uint32_t*>(&h);
}
__device__ __forceinline__ void ldm4(uint32_t r[4], uint32_t a) {
    asm volatile("ldmatrix.sync.aligned.m8n8.x4.shared.b16 {%0,%1,%2,%3}, [%4];"
        : "=r"(r[0]), "=r"(r[1]), "=r"(r[2]), "=r"(r[3]) : "r"(a));
}
__device__ __forceinline__ void mma16816(float c[4], const uint32_t a[4],
                                         uint32_t b0, uint32_t b1) {
    asm volatile(
        "mma.sync.aligned.m16n8k16.row.col.f32.f16.f16.f32 "
        "{%0,%1,%2,%3}, {%4,%5,%6,%7}, {%8,%9}, {%0,%1,%2,%3};"
        : "+f"(c[0]), "+f"(c[1]), "+f"(c[2]), "+f"(c[3])
        : "r"(a[0]), "r"(a[1]), "r"(a[2]), "r"(a[3]), "r"(b0), "r"(b1));
}

template<int NTOT, bool GATHER_A, bool SCATTER_OUT>
__global__ __launch_bounds__(256, 2)
void gemm_f16(const float* __restrict__ A, const float* __restrict__ B,
              const float* __restrict__ bias, float* __restrict__ Cout)
{
    __shared__ __align__(16) __half smA[2][128][PADH];
    __shared__ __align__(16) __half smB[2][128][PADH];

    const int tid  = threadIdx.x;
    const int lane = tid & 31;
    const int warp = tid >> 5;
    const int wm = (warp & 1) * 64;
    const int wn = (warp >> 1) * 32;
    const int g  = lane >> 2;
    const int q  = lane & 3;

    const int m0 = blockIdx.y * TBM;
    const int n0 = blockIdx.x * TBN;

    // ---- staging geometry: 2 threads per row, 16 fp32 each ----
    const int lrow = tid >> 1;
    const int lc   = (tid & 1) * 16;
    const long a_base = (GATHER_A ? (long)row_offset(m0 + lrow)
                                  : (long)(m0 + lrow) * KDIM) + lc;
    const long b_base = (long)(n0 + lrow) * KDIM + lc;

    // ---- ldmatrix lane geometry ----
    const uint32_t sA = (uint32_t)__cvta_generic_to_shared(&smA[0][0][0]);
    const uint32_t sB = (uint32_t)__cvta_generic_to_shared(&smB[0][0][0]);
    const int a_rin = (lane & 7) + ((lane >> 3) & 1) * 8;  // row within 16
    const int a_kof = (lane >> 4) * 8;                     // k 0 / 8
    const uint32_t aAddr = sA + (uint32_t)((wm + a_rin) * PADH + a_kof) * 2;
    const int b_rin = (lane & 7) + ((lane >> 4) & 1) * 8;  // n within 16
    const int b_kof = ((lane >> 3) & 1) * 8;
    const uint32_t bAddr = sB + (uint32_t)((wn + b_rin) * PADH + b_kof) * 2;

    float acc[4][4][4];
    #pragma unroll
    for (int i = 0; i < 4; i++)
        #pragma unroll
        for (int j = 0; j < 4; j++)
            #pragma unroll
            for (int c = 0; c < 4; c++) acc[i][j][c] = 0.f;

    uint32_t pa[8], pb[8];
    auto ldchunk = [&](int kc) {
        const float* ga = A + a_base + kc;
        const float* gb = B + b_base + kc;
        #pragma unroll
        for (int i = 0; i < 4; i++) {
            float4 v = *(const float4*)(ga + i * 4);
            pa[2*i]   = pkh2(v.x, v.y);
            pa[2*i+1] = pkh2(v.z, v.w);
            float4 w = *(const float4*)(gb + i * 4);
            pb[2*i]   = pkh2(w.x, w.y);
            pb[2*i+1] = pkh2(w.z, w.w);
        }
    };
    auto stchunk = [&](int buf) {
        #pragma unroll
        for (int i = 0; i < 4; i++) {
            *(uint2*)&smA[buf][lrow][lc + i * 4] = make_uint2(pa[2*i], pa[2*i+1]);
            *(uint2*)&smB[buf][lrow][lc + i * 4] = make_uint2(pb[2*i], pb[2*i+1]);
        }
    };

    ldchunk(0);
    stchunk(0);
    __syncthreads();

    const int NT = KDIM / TBK;   // 8
    #pragma unroll 1
    for (int c = 0; c < NT; ++c) {
        if (c + 1 < NT) ldchunk((c + 1) * TBK);

        const uint32_t ab = aAddr + (uint32_t)(c & 1) * BUFB;
        const uint32_t bb = bAddr + (uint32_t)(c & 1) * BUFB;
        #pragma unroll
        for (int kk = 0; kk < 2; kk++) {
            const uint32_t ko = (uint32_t)(kk * 16) * 2;   // byte offset
            uint32_t af[4][4], bf0[4], bf1[4];
            #pragma unroll
            for (int mt = 0; mt < 4; mt++)
                ldm4(af[mt], ab + (uint32_t)(mt * 16 * PADH * 2) + ko);
            ldm4(bf0, bb + ko);                                  // n 0-15
            ldm4(bf1, bb + (uint32_t)(16 * PADH * 2) + ko);      // n 16-31
            // bf regs: [0]=(n0-7 lo),[1]=(n0-7 hi),[2]=(n8-15 lo),[3]=(n8-15 hi)
            #pragma unroll
            for (int mt = 0; mt < 4; mt++) {
                mma16816(acc[mt][0], af[mt], bf0[0], bf0[1]);
                mma16816(acc[mt][1], af[mt], bf0[2], bf0[3]);
                mma16816(acc[mt][2], af[mt], bf1[0], bf1[1]);
                mma16816(acc[mt][3], af[mt], bf1[2], bf1[3]);
            }
        }

        if (c + 1 < NT) stchunk((c + 1) & 1);
        __syncthreads();
    }

    // epilogue: c0,c1 = (row g, cols 2q,2q+1); c2,c3 = row g+8
    #pragma unroll
    for (int mt = 0; mt < 4; mt++) {
        #pragma unroll
        for (int ri = 0; ri < 2; ri++) {
            const int m = m0 + wm + mt * 16 + g + ri * 8;
            const long ob = SCATTER_OUT ? (long)row_offset(m) : (long)m * NTOT;
            #pragma unroll
            for (int nt = 0; nt < 4; nt++) {
                const int col = n0 + wn + nt * 8 + 2 * q;
                float2 v;
                v.x = acc[mt][nt][ri * 2 + 0];
                v.y = acc[mt][nt][ri * 2 + 1];
                if (SCATTER_OUT) {
                    v.x += bias[col];
                    v.y += bias[col + 1];
                }
                *(float2*)(Cout + ob + col) = v;
            }
        }
    }
}

// ---------------------------------------------------------------------------
// Per-token head-mixing attention (8x8 over heads), fp32.
// ---------------------------------------------------------------------------
#define ATT_TOK 14
#define ATT_THREADS (ATT_TOK * 8)

__global__ __launch_bounds__(ATT_THREADS)
void attn_kernel(const float* __restrict__ qkv, float* __restrict__ att)
{
    __shared__ float rows[ATT_TOK][776];

    const int tid  = threadIdx.x;
    const int tok0 = blockIdx.x * ATT_TOK;

    for (int i = tid; i < ATT_TOK * 192; i += ATT_THREADS) {
        int t = i / 192, c4 = (i - t * 192) * 4;
        *(float4*)&rows[t][c4] =
            *(const float4*)(qkv + (size_t)(tok0 + t) * QKV_N + c4);
    }
    __syncthreads();

    const int t = tid >> 3;
    const int h = tid & 7;
    const float* row = rows[t];

    float qv[32];
    #pragma unroll
    for (int d = 0; d < 32; d++) qv[d] = row[h * 32 + d];

    const float scale = 0.17677669529663687f;
    float a[8];
    #pragma unroll
    for (int e = 0; e < 8; e++) {
        float acc = 0.f;
        #pragma unroll
        for (int d = 0; d < 32; d++) acc += qv[d] * row[256 + e * 32 + d];
        a[e] = acc * scale;
    }

    float mx = a[0];
    #pragma unroll
    for (int e = 1; e < 8; e++) mx = fmaxf(mx, a[e]);
    float sum = 0.f;
    #pragma unroll
    for (int e = 0; e < 8; e++) { a[e] = __expf(a[e] - mx); sum += a[e]; }
    float inv = 1.f / sum;
    #pragma unroll
    for (int e = 0; e < 8; e++) a[e] *= inv;

    const int n = tok0 + t;
    const int w = n / 49;
    const int s = n - w * 49;
    float* op = att + (size_t)w * 12544 + h * 1568 + s * 32;

    #pragma unroll
    for (int d = 0; d < 32; d += 4) {
        float4 o;
        o.x = o.y = o.z = o.w = 0.f;
        #pragma unroll
        for (int e = 0; e < 8; e++) {
            const float* vp = &row[512 + e * 32 + d];
            o.x += a[e] * vp[0];
            o.y += a[e] * vp[1];
            o.z += a[e] * vp[2];
            o.w += a[e] * vp[3];
        }
        *(float4*)(op + d) = o;
    }
}

// ---------------------------------------------------------------------------
extern "C" void kernel_launch(void* const* d_in, const int* in_sizes, int n_in,
                              void* d_out, int out_size)
{
    (void)in_sizes; (void)n_in; (void)out_size;
    const float* x      = (const float*)d_in[0];
    const float* w_qkv  = (const float*)d_in[1];
    const float* w_proj = (const float*)d_in[2];
    const float* b_proj = (const float*)d_in[3];
    float* out = (float*)d_out;

    void* qkv_ptr = nullptr;
    void* att_ptr = nullptr;
    cudaGetSymbolAddress(&qkv_ptr, g_qkv);
    cudaGetSymbolAddress(&att_ptr, g_att);
    float* qkv = (float*)qkv_ptr;
    float* att = (float*)att_ptr;

    {
        dim3 grid(QKV_N / TBN, M_TOK / TBM);   // (6, 784)
        gemm_f16<QKV_N, true, false><<<grid, 256>>>(x, w_qkv, nullptr, qkv);
    }
    {
        attn_kernel<<<M_TOK / ATT_TOK, ATT_THREADS>>>(qkv, att);
    }
    {
        dim3 grid(KDIM / TBN, M_TOK / TBM);    // (2, 784)
        gemm_f16<KDIM, false, true><<<grid, 256>>>(att, w_proj, b_proj, out);
    }
}

// round 11
// speedup vs baseline: 1.8441x; 1.8441x over previous
#include <cuda_runtime.h>
#include <cuda_fp16.h>
#include <cstdint>

// ---------------------------------------------------------------------------
// WindowAttention (reference semantics):
//   qkv = window_gather(x) @ w_qkv^T          [100352 x 768]
//   per token: A[h,e] = softmax_e(q_h . k_e / sqrt(32));  o_h = sum_e A[h,e] v_e
//   att layout per window: h*1568 + s*32 + d  (swapaxes(1,2) flatten)
//   out = att @ w_proj^T + b, window-scattered back to (32,56,56,256)
//
// GEMMs: fp16 m16n8k16. Operands PRE-CONVERTED to fp16 in gmem with k16
// interleave (slot(r) = (r&1)|((r>>3)&1)<<1|((r>>1)&3)<<2) so each thread's
// fragment halves are contiguous -> 1 LDS.64 per fragment pair, no in-loop
// cvt. 4-stage cp.async pipeline, pad-48-half rows (conflict-free).
// ---------------------------------------------------------------------------

#define M_TOK 100352
#define KDIM  256
#define QKV_N 768

__device__ float  g_qkv[(size_t)M_TOK * QKV_N];            // 308 MB fp32
__device__ __half g_att16[(size_t)M_TOK * KDIM];           // 51 MB fp16 (interleaved)
__device__ __half g_x16[(size_t)32 * 56 * 56 * 256];       // 51 MB
__device__ __half g_wqkv16[(size_t)QKV_N * KDIM];
__device__ __half g_wproj16[(size_t)KDIM * KDIM];

__device__ __host__ __forceinline__ int kslot(int r) {
    return (r & 1) | (((r >> 3) & 1) << 1) | (((r >> 1) & 3) << 2);
}

__device__ __forceinline__ int row_offset(int n) {
    int w  = n / 49;
    int s  = n - w * 49;
    int b  = w >> 6;
    int wh = (w >> 3) & 7;
    int ww = w & 7;
    int r  = s / 7;
    int cc = s - r * 7;
    int hh = wh * 7 + r;
    int wc = ww * 7 + cc;
    return ((b * 56 + hh) * 56 + wc) * 256;
}

// ---------------- fp32 -> fp16 with k16 interleave -------------------------
__global__ void cvt16(const float* __restrict__ in, __half* __restrict__ out,
                      int ngroups)
{
    int i = blockIdx.x * blockDim.x + threadIdx.x;
    if (i >= ngroups) return;
    const float4* p = (const float4*)(in + (size_t)i * 16);
    float f[16];
    *(float4*)&f[0]  = p[0];
    *(float4*)&f[4]  = p[1];
    *(float4*)&f[8]  = p[2];
    *(float4*)&f[12] = p[3];
    __half t[16];
    #pragma unroll
    for (int r = 0; r < 16; r++) t[kslot(r)] = __float2half_rn(f[r]);
    uint4* o = (uint4*)(out + (size_t)i * 16);
    o[0] = *(uint4*)&t[0];
    o[1] = *(uint4*)&t[8];
}

// ---------------------------------------------------------------------------
// fp16 TC GEMM: C[M x NTOT] = A[M x 256] * B[NTOT x 256]^T, fp32 out.
// 128x128 tile, chunks of k=32, 4-stage cp.async, 8 warps x (64x32).
// ---------------------------------------------------------------------------
#define TBM 128
#define TBN 128
#define PADH 48                        // halves per chunk-row (96 B)
#define STG_H (128 * PADH)             // halves per matrix per stage (6144)
#define STG_B (2 * STG_H * 2)          // bytes per stage (A+B) = 24576
#define SMEMB (4 * STG_B)              // 98304

__device__ __forceinline__ void cpa16(uint32_t s, const void* g) {
    asm volatile("cp.async.cg.shared.global [%0], [%1], 16;" :: "r"(s), "l"(g));
}
__device__ __forceinline__ uint2 lds64(uint32_t a) {
    uint2 r;
    asm volatile("ld.shared.v2.b32 {%0,%1}, [%2];" : "=r"(r.x), "=r"(r.y) : "r"(a));
    return r;
}
__device__ __forceinline__ void mma16816(float c[4], uint32_t a0, uint32_t a1,
                                         uint32_t a2, uint32_t a3,
                                         uint32_t b0, uint32_t b1) {
    asm volatile(
        "mma.sync.aligned.m16n8k16.row.col.f32.f16.f16.f32 "
        "{%0,%1,%2,%3}, {%4,%5,%6,%7}, {%8,%9}, {%0,%1,%2,%3};"
        : "+f"(c[0]), "+f"(c[1]), "+f"(c[2]), "+f"(c[3])
        : "r"(a0), "r"(a1), "r"(a2), "r"(a3), "r"(b0), "r"(b1));
}

template<int NTOT, bool GATHER_A, bool SCATTER_OUT>
__global__ __launch_bounds__(256, 2)
void gemm_h(const __half* __restrict__ A, const __half* __restrict__ B,
            const float* __restrict__ bias, float* __restrict__ Cout)
{
    extern __shared__ __align__(16) __half sh[];
    const uint32_t sb = (uint32_t)__cvta_generic_to_shared(sh);

    const int tid  = threadIdx.x;
    const int lane = tid & 31;
    const int warp = tid >> 5;
    const int wm = (warp & 1) * 64;
    const int wn = (warp >> 1) * 32;
    const int g  = lane >> 2;
    const int q  = lane & 3;

    const int m0 = blockIdx.y * TBM;
    const int n0 = blockIdx.x * TBN;

    // loader: 2 threads per row, 16 halves (32B) each
    const int lrow = tid >> 1;
    const int lh   = (tid & 1) * 16;
    const long a_base = (GATHER_A ? (long)row_offset(m0 + lrow)
                                  : (long)(m0 + lrow) * KDIM) + lh;
    const long b_base = (long)(n0 + lrow) * KDIM + lh;
    const uint32_t sts_a = sb + (uint32_t)(lrow * PADH + lh) * 2;
    const uint32_t sts_b = sts_a + STG_H * 2;

    // fragment bases (bytes): row*96 + q*8
    const uint32_t aAddr = sb + (uint32_t)((wm + g) * PADH) * 2 + (uint32_t)(q * 8);
    const uint32_t bAddr = sb + (uint32_t)STG_H * 2
                         + (uint32_t)((wn + g) * PADH) * 2 + (uint32_t)(q * 8);

    float acc[4][4][4];
    #pragma unroll
    for (int i = 0; i < 4; i++)
        #pragma unroll
        for (int j = 0; j < 4; j++)
            #pragma unroll
            for (int c = 0; c < 4; c++) acc[i][j][c] = 0.f;

    auto stage = [&](int s, int k0) {
        const __half* ag = A + a_base + k0;
        const __half* bg = B + b_base + k0;
        const uint32_t so = (uint32_t)(s * STG_B);
        cpa16(sts_a + so,      ag);
        cpa16(sts_a + so + 16, ag + 8);
        cpa16(sts_b + so,      bg);
        cpa16(sts_b + so + 16, bg + 8);
        asm volatile("cp.async.commit_group;");
    };

    stage(0, 0);
    stage(1, 32);
    stage(2, 64);

    const int NT = KDIM / 32;   // 8
    #pragma unroll 1
    for (int t = 0; t < NT; ++t) {
        asm volatile("cp.async.wait_group 2;");
        __syncthreads();
        if (t + 3 < NT) stage((t + 3) & 3, (t + 3) * 32);

        const uint32_t so = (uint32_t)((t & 3) * STG_B);
        const uint32_t ab = aAddr + so;
        const uint32_t bb = bAddr + so;
        #pragma unroll
        for (int kk = 0; kk < 2; kk++) {
            const uint32_t ko = (uint32_t)(kk * 32);   // 16 halves per k16 group
            uint32_t af[4][4];
            #pragma unroll
            for (int mt = 0; mt < 4; mt++) {
                uint2 lo = lds64(ab + (uint32_t)(mt * 16 * PADH * 2) + ko);
                uint2 hi = lds64(ab + (uint32_t)((mt * 16 + 8) * PADH * 2) + ko);
                af[mt][0] = lo.x; af[mt][1] = hi.x;
                af[mt][2] = lo.y; af[mt][3] = hi.y;
            }
            #pragma unroll
            for (int nt = 0; nt < 4; nt++) {
                uint2 b2 = lds64(bb + (uint32_t)(nt * 8 * PADH * 2) + ko);
                #pragma unroll
                for (int mt = 0; mt < 4; mt++)
                    mma16816(acc[mt][nt], af[mt][0], af[mt][1], af[mt][2],
                             af[mt][3], b2.x, b2.y);
            }
        }
        __syncthreads();
    }

    // epilogue: c0,c1 = (row g, cols 2q,2q+1); c2,c3 = row g+8
    #pragma unroll
    for (int mt = 0; mt < 4; mt++) {
        #pragma unroll
        for (int ri = 0; ri < 2; ri++) {
            const int m = m0 + wm + mt * 16 + g + ri * 8;
            const long ob = SCATTER_OUT ? (long)row_offset(m) : (long)m * NTOT;
            #pragma unroll
            for (int nt = 0; nt < 4; nt++) {
                const int col = n0 + wn + nt * 8 + 2 * q;
                float2 v;
                v.x = acc[mt][nt][ri * 2 + 0];
                v.y = acc[mt][nt][ri * 2 + 1];
                if (SCATTER_OUT) {
                    v.x += bias[col];
                    v.y += bias[col + 1];
                }
                *(float2*)(Cout + ob + col) = v;
            }
        }
    }
}

// ---------------------------------------------------------------------------
// Per-token head-mixing attention (8x8 over heads), fp32 compute,
// fp16 interleaved output.
// ---------------------------------------------------------------------------
#define ATT_TOK 14
#define ATT_THREADS (ATT_TOK * 8)

__global__ __launch_bounds__(ATT_THREADS)
void attn_kernel(const float* __restrict__ qkv, __half* __restrict__ att)
{
    __shared__ float rows[ATT_TOK][776];

    const int tid  = threadIdx.x;
    const int tok0 = blockIdx.x * ATT_TOK;

    for (int i = tid; i < ATT_TOK * 192; i += ATT_THREADS) {
        int t = i / 192, c4 = (i - t * 192) * 4;
        *(float4*)&rows[t][c4] =
            *(const float4*)(qkv + (size_t)(tok0 + t) * QKV_N + c4);
    }
    __syncthreads();

    const int t = tid >> 3;
    const int h = tid & 7;
    const float* row = rows[t];

    float qv[32];
    #pragma unroll
    for (int d = 0; d < 32; d++) qv[d] = row[h * 32 + d];

    const float scale = 0.17677669529663687f;
    float a[8];
    #pragma unroll
    for (int e = 0; e < 8; e++) {
        float acc = 0.f;
        #pragma unroll
        for (int d = 0; d < 32; d++) acc += qv[d] * row[256 + e * 32 + d];
        a[e] = acc * scale;
    }

    float mx = a[0];
    #pragma unroll
    for (int e = 1; e < 8; e++) mx = fmaxf(mx, a[e]);
    float sum = 0.f;
    #pragma unroll
    for (int e = 0; e < 8; e++) { a[e] = __expf(a[e] - mx); sum += a[e]; }
    float inv = 1.f / sum;
    #pragma unroll
    for (int e = 0; e < 8; e++) a[e] *= inv;

    float o[32];
    #pragma unroll
    for (int d = 0; d < 32; d++) {
        float acc = 0.f;
        #pragma unroll
        for (int e = 0; e < 8; e++) acc += a[e] * row[512 + e * 32 + d];
        o[d] = acc;
    }

    // fp16 + k16 interleave, layout w*12544 + h*1568 + s*32 + d
    const int n = tok0 + t;
    const int w = n / 49;
    const int s = n - w * 49;
    __half* op = att + (size_t)w * 12544 + h * 1568 + s * 32;

    __half tmp[32];
    #pragma unroll
    for (int d = 0; d < 32; d++) {
        int g16 = d >> 4, r = d & 15;
        tmp[g16 * 16 + kslot(r)] = __float2half_rn(o[d]);
    }
    uint4* ov = (uint4*)op;
    ov[0] = *(uint4*)&tmp[0];
    ov[1] = *(uint4*)&tmp[8];
    ov[2] = *(uint4*)&tmp[16];
    ov[3] = *(uint4*)&tmp[24];
}

// ---------------------------------------------------------------------------
extern "C" void kernel_launch(void* const* d_in, const int* in_sizes, int n_in,
                              void* d_out, int out_size)
{
    (void)in_sizes; (void)n_in; (void)out_size;
    const float* x      = (const float*)d_in[0];
    const float* w_qkv  = (const float*)d_in[1];
    const float* w_proj = (const float*)d_in[2];
    const float* b_proj = (const float*)d_in[3];
    float* out = (float*)d_out;

    void *qkv_p, *att_p, *x16_p, *wq16_p, *wp16_p;
    cudaGetSymbolAddress(&qkv_p, g_qkv);
    cudaGetSymbolAddress(&att_p, g_att16);
    cudaGetSymbolAddress(&x16_p, g_x16);
    cudaGetSymbolAddress(&wq16_p, g_wqkv16);
    cudaGetSymbolAddress(&wp16_p, g_wproj16);
    float*  qkv  = (float*)qkv_p;
    __half* att  = (__half*)att_p;
    __half* x16  = (__half*)x16_p;
    __half* wq16 = (__half*)wq16_p;
    __half* wp16 = (__half*)wp16_p;

    static bool attr_done = false;
    if (!attr_done) {
        cudaFuncSetAttribute(gemm_h<QKV_N, true, false>,
                             cudaFuncAttributeMaxDynamicSharedMemorySize, SMEMB);
        cudaFuncSetAttribute(gemm_h<KDIM, false, true>,
                             cudaFuncAttributeMaxDynamicSharedMemorySize, SMEMB);
        attr_done = true;
    }

    // 0) fp32 -> fp16 (k16-interleaved) conversions
    {
        int ngx = 32 * 56 * 56 * 256 / 16;          // 1605632
        cvt16<<<(ngx + 255) / 256, 256>>>(x, x16, ngx);
        int ngq = QKV_N * KDIM / 16;                // 12288
        cvt16<<<(ngq + 255) / 256, 256>>>(w_qkv, wq16, ngq);
        int ngp = KDIM * KDIM / 16;                 // 4096
        cvt16<<<(ngp + 255) / 256, 256>>>(w_proj, wp16, ngp);
    }
    // 1) QKV projection (gathered A)
    {
        dim3 grid(QKV_N / TBN, M_TOK / TBM);   // (6, 784)
        gemm_h<QKV_N, true, false><<<grid, 256, SMEMB>>>(x16, wq16, nullptr, qkv);
    }
    // 2) attention (writes fp16 interleaved att)
    {
        attn_kernel<<<M_TOK / ATT_TOK, ATT_THREADS>>>(qkv, att);
    }
    // 3) output projection + bias + scatter
    {
        dim3 grid(KDIM / TBN, M_TOK / TBM);    // (2, 784)
        gemm_h<KDIM, false, true><<<grid, 256, SMEMB>>>(att, wp16, b_proj, out);
    }
}